// round 16
// baseline (speedup 1.0000x reference)
#include <cuda_runtime.h>
#include <cuda_fp16.h>
#include <cstdint>

// Problem constants
#define BSZ 2
#define SEQ 2048
#define DM 1024
#define NH 16
#define HD 64
#define MROWS 4096
#define QKV_N 3072
#define KDIM 1024

// ---------------------------------------------------------------------------
// Scratch (__device__ globals; allocation-free rule). Weights kept [K,N].
// ---------------------------------------------------------------------------
__device__ __align__(16) __half g_xh[MROWS * KDIM];        // x single fp16
__device__ __align__(16) __half g_wqh[KDIM * QKV_N];       // w_qkv [K,N] single
__device__ __align__(16) __half g_woh[KDIM * DM];          // w_out [K,N] hi
__device__ __align__(16) __half g_wol[KDIM * DM];          // w_out [K,N] lo
__device__ __align__(16) __half g_qkvh[MROWS * QKV_N];     // Q(scaled) K V single
__device__ __align__(16) __half g_ath[MROWS * DM];         // attn out single

// ---------------------------------------------------------------------------
// PTX helpers
// ---------------------------------------------------------------------------
__device__ __forceinline__ uint32_t smem_u32(const void* p) {
    uint32_t a;
    asm("{ .reg .u64 t; cvta.to.shared.u64 t, %1; cvt.u32.u64 %0, t; }" : "=r"(a) : "l"(p));
    return a;
}
__device__ __forceinline__ void ldmx4(uint32_t& r0, uint32_t& r1, uint32_t& r2,
                                      uint32_t& r3, uint32_t addr) {
    asm volatile("ldmatrix.sync.aligned.m8n8.x4.shared.b16 {%0,%1,%2,%3}, [%4];"
                 : "=r"(r0), "=r"(r1), "=r"(r2), "=r"(r3) : "r"(addr));
}
__device__ __forceinline__ void ldmx4t(uint32_t& r0, uint32_t& r1, uint32_t& r2,
                                       uint32_t& r3, uint32_t addr) {
    asm volatile("ldmatrix.sync.aligned.m8n8.x4.trans.shared.b16 {%0,%1,%2,%3}, [%4];"
                 : "=r"(r0), "=r"(r1), "=r"(r2), "=r"(r3) : "r"(addr));
}
__device__ __forceinline__ void mma_f16(float* c, const uint32_t* a, const uint32_t* b) {
    asm volatile(
        "mma.sync.aligned.m16n8k16.row.col.f32.f16.f16.f32 "
        "{%0,%1,%2,%3}, {%4,%5,%6,%7}, {%8,%9}, {%0,%1,%2,%3};"
        : "+f"(c[0]), "+f"(c[1]), "+f"(c[2]), "+f"(c[3])
        : "r"(a[0]), "r"(a[1]), "r"(a[2]), "r"(a[3]), "r"(b[0]), "r"(b[1]));
}
__device__ __forceinline__ void cp_async16(uint32_t saddr, const void* g) {
    asm volatile("cp.async.cg.shared.global [%0], [%1], 16;" :: "r"(saddr), "l"(g));
}
#define CP_COMMIT() asm volatile("cp.async.commit_group;" ::: "memory")
#define CP_WAIT(n)  asm volatile("cp.async.wait_group %0;" :: "n"(n) : "memory")

__device__ __forceinline__ uint32_t pack2h(__half a, __half b) {
    __half2 t = __halves2half2(a, b);
    return *reinterpret_cast<uint32_t*>(&t);
}
__device__ __forceinline__ void split2h(float a, float b, uint32_t& hi, uint32_t& lo) {
    __half ha = __float2half_rn(a), hb = __float2half_rn(b);
    hi = pack2h(ha, hb);
    lo = pack2h(__float2half_rn(a - __half2float(ha)),
                __float2half_rn(b - __half2float(hb)));
}

// ---------------------------------------------------------------------------
// Preprocessing (elementwise only — no transposes)
// ---------------------------------------------------------------------------
__global__ __launch_bounds__(256) void to_f16(
    const float* __restrict__ src, __half* __restrict__ dst, int n)
{
    int i = (blockIdx.x * 256 + threadIdx.x) * 4;
    if (i >= n) return;
    float4 v = *(const float4*)&src[i];
    uint2 o;
    o.x = pack2h(__float2half_rn(v.x), __float2half_rn(v.y));
    o.y = pack2h(__float2half_rn(v.z), __float2half_rn(v.w));
    *(uint2*)&dst[i] = o;
}

__global__ __launch_bounds__(256) void split_f16(
    const float* __restrict__ src, __half* __restrict__ hi,
    __half* __restrict__ lo, int n)
{
    int i = (blockIdx.x * 256 + threadIdx.x) * 4;
    if (i >= n) return;
    float4 v = *(const float4*)&src[i];
    uint32_t h0, l0, h1, l1;
    split2h(v.x, v.y, h0, l0);
    split2h(v.z, v.w, h1, l1);
    *(uint2*)&hi[i] = make_uint2(h0, h1);
    *(uint2*)&lo[i] = make_uint2(l0, l1);
}

// ---------------------------------------------------------------------------
// GEMM tiles: A [128 rows][BKP] (ldmx4), B [32 k-rows][BNP] (ldmx4t, [K,N]).
// 128x128 CTA, BK=32, 8 warps (2m x 4n), warp 64x32.
// QKV: 3-stage pipeline, 3 CTAs/SM. Out: 2-stage, 3 CTAs/SM.
// ---------------------------------------------------------------------------
#define BKP 40
#define BNP 136
#define TSA (128 * BKP)               // 5120 elems
#define TSB (32 * BNP)                // 4352 elems
#define Q_STG (TSA + TSB)             // 9472 elems
#define QKV_DSMEM (3 * Q_STG * 2)     // 56,832 B (x3 CTAs = 170 KB)
#define O_STG (TSA + 2 * TSB)         // 13,824 elems
#define OUT_DSMEM (2 * O_STG * 2)     // 55,296 B (x3 CTAs = 166 KB)

// ---------------------------------------------------------------------------
// QKV GEMM: A single x B single (trans-B), 1 MMA. 3 CTAs/SM.
// ---------------------------------------------------------------------------
__global__ __launch_bounds__(256, 3) void gemm_qkv(
    const __half* __restrict__ A, const __half* __restrict__ B,
    const float* __restrict__ bias)
{
    extern __shared__ __align__(16) __half qbase[];
    const int tid  = threadIdx.x;
    const int lane = tid & 31;
    const int wid  = tid >> 5;
    const int warp_m = (wid & 1) * 64;
    const int warp_n = (wid >> 1) * 32;
    const int brow = blockIdx.y * 128;
    const int bcol = blockIdx.x * 128;

    float acc[4][4][4];
#pragma unroll
    for (int mi = 0; mi < 4; mi++)
#pragma unroll
        for (int ni = 0; ni < 4; ni++)
#pragma unroll
            for (int j = 0; j < 4; j++) acc[mi][ni][j] = 0.0f;

    const int a_row = (lane & 7) + ((lane >> 3) & 1) * 8;
    const int a_kh  = (lane >> 4) * 8;
    const int trow  = lane & 15;
    const int tcol8 = ((lane >> 4) & 1) * 8;

#define Q_ISSUE(s_, buf_)                                                         \
    do {                                                                          \
        __half* st = qbase + (buf_) * Q_STG;                                      \
        _Pragma("unroll") for (int u = tid; u < 1024; u += 256) {                 \
            if (u < 512) {                                                        \
                const int row = u >> 2;                                           \
                const int c8 = (u & 3) * 8;                                       \
                const size_t ga = (size_t)(brow + row) * KDIM + (s_) * 32 + c8;   \
                cp_async16(smem_u32(st + row * BKP + c8), &A[ga]);                \
            } else {                                                              \
                const int v = u - 512;                                            \
                const int row = v >> 4;                                           \
                const int c8 = (v & 15) * 8;                                      \
                const size_t gb = (size_t)((s_) * 32 + row) * QKV_N + bcol + c8;  \
                cp_async16(smem_u32(st + TSA + row * BNP + c8), &B[gb]);          \
            }                                                                     \
        }                                                                         \
    } while (0)

    Q_ISSUE(0, 0); CP_COMMIT();
    Q_ISSUE(1, 1); CP_COMMIT();
    const int NS = KDIM / 32;
    for (int s = 0; s < NS; s++) {
        if (s + 2 < NS) { Q_ISSUE(s + 2, (s + 2) % 3); CP_COMMIT(); CP_WAIT(2); }
        else if (s + 1 < NS) { CP_WAIT(1); }
        else { CP_WAIT(0); }
        __syncthreads();
        const __half* cA = qbase + (s % 3) * Q_STG;
        const __half* cB = qbase + (s % 3) * Q_STG + TSA;
#pragma unroll
        for (int kk = 0; kk < 2; kk++) {
            const int k0 = kk * 16;
            uint32_t af[4][4], bf[4][2];
#pragma unroll
            for (int mi = 0; mi < 4; mi++) {
                const int r = warp_m + mi * 16 + a_row;
                ldmx4(af[mi][0], af[mi][1], af[mi][2], af[mi][3],
                      smem_u32(&cA[r * BKP + k0 + a_kh]));
            }
#pragma unroll
            for (int pr = 0; pr < 2; pr++) {
                ldmx4t(bf[2 * pr][0], bf[2 * pr][1], bf[2 * pr + 1][0],
                       bf[2 * pr + 1][1],
                       smem_u32(&cB[(k0 + trow) * BNP + warp_n + pr * 16 + tcol8]));
            }
#pragma unroll
            for (int mi = 0; mi < 4; mi++)
#pragma unroll
                for (int ni = 0; ni < 4; ni++)
                    mma_f16(acc[mi][ni], af[mi], bf[ni]);
        }
        __syncthreads();
    }

    const int er = brow + warp_m + (lane >> 2);
    const int ec = bcol + warp_n + (lane & 3) * 2;
#pragma unroll
    for (int mi = 0; mi < 4; mi++)
#pragma unroll
        for (int ni = 0; ni < 4; ni++) {
            const int r0 = er + mi * 16;
            const int c0 = ec + ni * 8;
            float v0 = acc[mi][ni][0] + bias[c0];
            float v1 = acc[mi][ni][1] + bias[c0 + 1];
            float v2 = acc[mi][ni][2] + bias[c0];
            float v3 = acc[mi][ni][3] + bias[c0 + 1];
            if (c0 < DM) { v0 *= 0.03125f; v1 *= 0.03125f; v2 *= 0.03125f; v3 *= 0.03125f; }
            *(uint32_t*)&g_qkvh[(size_t)r0 * QKV_N + c0] =
                pack2h(__float2half_rn(v0), __float2half_rn(v1));
            *(uint32_t*)&g_qkvh[(size_t)(r0 + 8) * QKV_N + c0] =
                pack2h(__float2half_rn(v2), __float2half_rn(v3));
        }
}

// ---------------------------------------------------------------------------
// Out-proj GEMM: A single x B 2-term (trans-B), 2 MMAs. 2-stage, 3 CTAs/SM.
// ---------------------------------------------------------------------------
__global__ __launch_bounds__(256, 3) void gemm_out(
    const __half* __restrict__ A, const __half* __restrict__ Bh,
    const __half* __restrict__ Bl, const float* __restrict__ bias,
    float* __restrict__ C)
{
    extern __shared__ __align__(16) __half obase[];
    const int tid  = threadIdx.x;
    const int lane = tid & 31;
    const int wid  = tid >> 5;
    const int warp_m = (wid & 1) * 64;
    const int warp_n = (wid >> 1) * 32;
    const int brow = blockIdx.y * 128;
    const int bcol = blockIdx.x * 128;

    float acc[4][4][4];
#pragma unroll
    for (int mi = 0; mi < 4; mi++)
#pragma unroll
        for (int ni = 0; ni < 4; ni++)
#pragma unroll
            for (int j = 0; j < 4; j++) acc[mi][ni][j] = 0.0f;

    const int a_row = (lane & 7) + ((lane >> 3) & 1) * 8;
    const int a_kh  = (lane >> 4) * 8;
    const int trow  = lane & 15;
    const int tcol8 = ((lane >> 4) & 1) * 8;

#define O_ISSUE(s_, buf_)                                                         \
    do {                                                                          \
        __half* st = obase + (buf_) * O_STG;                                      \
        _Pragma("unroll") for (int u = tid; u < 1536; u += 256) {                 \
            if (u < 512) {                                                        \
                const int row = u >> 2;                                           \
                const int c8 = (u & 3) * 8;                                       \
                const size_t ga = (size_t)(brow + row) * KDIM + (s_) * 32 + c8;   \
                cp_async16(smem_u32(st + row * BKP + c8), &A[ga]);                \
            } else if (u < 1024) {                                                \
                const int v = u - 512;                                            \
                const int row = v >> 4;                                           \
                const int c8 = (v & 15) * 8;                                      \
                const size_t gb = (size_t)((s_) * 32 + row) * DM + bcol + c8;     \
                cp_async16(smem_u32(st + TSA + row * BNP + c8), &Bh[gb]);         \
            } else {                                                              \
                const int v = u - 1024;                                           \
                const int row = v >> 4;                                           \
                const int c8 = (v & 15) * 8;                                      \
                const size_t gb = (size_t)((s_) * 32 + row) * DM + bcol + c8;     \
                cp_async16(smem_u32(st + TSA + TSB + row * BNP + c8), &Bl[gb]);   \
            }                                                                     \
        }                                                                         \
    } while (0)

    O_ISSUE(0, 0);
    CP_COMMIT();
    const int NS = KDIM / 32;
    for (int s = 0; s < NS; s++) {
        if (s + 1 < NS) { O_ISSUE(s + 1, (s + 1) & 1); CP_COMMIT(); CP_WAIT(1); }
        else { CP_WAIT(0); }
        __syncthreads();
        const __half* cA  = obase + (s & 1) * O_STG;
        const __half* cBh = obase + (s & 1) * O_STG + TSA;
        const __half* cBl = obase + (s & 1) * O_STG + TSA + TSB;
#pragma unroll
        for (int kk = 0; kk < 2; kk++) {
            const int k0 = kk * 16;
            uint32_t af[4][4], bh[4][2], bl[4][2];
#pragma unroll
            for (int mi = 0; mi < 4; mi++) {
                const int r = warp_m + mi * 16 + a_row;
                ldmx4(af[mi][0], af[mi][1], af[mi][2], af[mi][3],
                      smem_u32(&cA[r * BKP + k0 + a_kh]));
            }
#pragma unroll
            for (int pr = 0; pr < 2; pr++) {
                const uint32_t off = (k0 + trow) * BNP + warp_n + pr * 16 + tcol8;
                ldmx4t(bh[2 * pr][0], bh[2 * pr][1], bh[2 * pr + 1][0],
                       bh[2 * pr + 1][1], smem_u32(&cBh[off]));
                ldmx4t(bl[2 * pr][0], bl[2 * pr][1], bl[2 * pr + 1][0],
                       bl[2 * pr + 1][1], smem_u32(&cBl[off]));
            }
#pragma unroll
            for (int mi = 0; mi < 4; mi++)
#pragma unroll
                for (int ni = 0; ni < 4; ni++) {
                    mma_f16(acc[mi][ni], af[mi], bh[ni]);
                    mma_f16(acc[mi][ni], af[mi], bl[ni]);
                }
        }
        __syncthreads();
    }

    const int er = brow + warp_m + (lane >> 2);
    const int ec = bcol + warp_n + (lane & 3) * 2;
#pragma unroll
    for (int mi = 0; mi < 4; mi++)
#pragma unroll
        for (int ni = 0; ni < 4; ni++) {
            const int r0 = er + mi * 16;
            const int c0 = ec + ni * 8;
            float2 v0, v1;
            v0.x = acc[mi][ni][0] + bias[c0];
            v0.y = acc[mi][ni][1] + bias[c0 + 1];
            v1.x = acc[mi][ni][2] + bias[c0];
            v1.y = acc[mi][ni][3] + bias[c0 + 1];
            *(float2*)&C[(size_t)r0 * DM + c0] = v0;
            *(float2*)&C[(size_t)(r0 + 8) * DM + c0] = v1;
        }
}

// ---------------------------------------------------------------------------
// Flash attention fp16 (validated R11, unchanged): S = QK 1 MMA, PV 1 MMA.
// ---------------------------------------------------------------------------
#define AT_TILE (64 * 72)
#define AT_STG (2 * AT_TILE)
#define ATTN_DSMEM (2 * AT_STG * 2)   // 36,864 B

__global__ __launch_bounds__(256) void flash_attn_f16()
{
    extern __shared__ __align__(16) __half abase[];

    const int tid = threadIdx.x, lane = tid & 31, wid = tid >> 5;
    const int qt = gridDim.x - 1 - blockIdx.x;
    const int h = blockIdx.y, b = blockIdx.z;
    const int q0 = qt * 128;
    const size_t rowb = (size_t)b * SEQ + q0;
    const int wm = wid * 16;
    const int ra = lane >> 2;
    const int kq = (lane & 3) * 2;

    uint32_t qf[4][4];
    {
        const size_t r0 = (rowb + wm + ra) * QKV_N + h * HD;
        const size_t r1 = (rowb + wm + ra + 8) * QKV_N + h * HD;
#pragma unroll
        for (int ks = 0; ks < 4; ks++) {
            const int c = ks * 16 + kq;
            qf[ks][0] = *(const uint32_t*)&g_qkvh[r0 + c];
            qf[ks][1] = *(const uint32_t*)&g_qkvh[r1 + c];
            qf[ks][2] = *(const uint32_t*)&g_qkvh[r0 + c + 8];
            qf[ks][3] = *(const uint32_t*)&g_qkvh[r1 + c + 8];
        }
    }

    float o[8][4];
#pragma unroll
    for (int dn = 0; dn < 8; dn++)
#pragma unroll
        for (int j = 0; j < 4; j++) o[dn][j] = 0.0f;
    float m_lo = -1e30f, m_hi = -1e30f, l_lo = 0.0f, l_hi = 0.0f;

    const int bx4_row = (lane & 7) + ((lane >> 4) & 1) * 8;
    const int b_kh = ((lane >> 3) & 1) * 8;
    const int v_row = lane & 15;
    const int v_ch = ((lane >> 4) & 1) * 8;

#define KV_ISSUE(kt_, buf_)                                                        \
    do {                                                                           \
        __half* st = abase + (buf_) * AT_STG;                                      \
        const size_t gr = (size_t)b * SEQ + (kt_) * 64;                            \
        _Pragma("unroll") for (int u = tid; u < 512; u += 256) {                   \
            const int row = u >> 3;                                                \
            const int c8 = (u & 7) * 8;                                            \
            const size_t gk = (gr + row) * QKV_N + DM + h * HD + c8;               \
            cp_async16(smem_u32(st + 0 * AT_TILE + row * 72 + c8), &g_qkvh[gk]);   \
            cp_async16(smem_u32(st + 1 * AT_TILE + row * 72 + c8), &g_qkvh[gk + DM]); \
        }                                                                          \
    } while (0)

    const int nkt = 2 * qt + 2;
    KV_ISSUE(0, 0);
    CP_COMMIT();

    for (int kt = 0; kt < nkt; kt++) {
        if (kt + 1 < nkt) { KV_ISSUE(kt + 1, (kt + 1) & 1); CP_COMMIT(); CP_WAIT(1); }
        else { CP_WAIT(0); }
        __syncthreads();
        const __half* sK = abase + (kt & 1) * AT_STG + 0 * AT_TILE;
        const __half* sV = abase + (kt & 1) * AT_STG + 1 * AT_TILE;
        const int t0 = kt * 64;

        float s[8][4];
#pragma unroll
        for (int nt = 0; nt < 8; nt++)
#pragma unroll
            for (int j = 0; j < 4; j++) s[nt][j] = 0.0f;
#pragma unroll
        for (int pr = 0; pr < 4; pr++) {
            const int r = pr * 16 + bx4_row;
#pragma unroll
            for (int ks = 0; ks < 4; ks++) {
                uint32_t k0f[2], k1f[2];
                ldmx4(k0f[0], k0f[1], k1f[0], k1f[1],
                      smem_u32(&sK[r * 72 + ks * 16 + b_kh]));
                mma_f16(s[2 * pr], qf[ks], k0f);
                mma_f16(s[2 * pr + 1], qf[ks], k1f);
            }
        }

        if (t0 + 63 > q0 + wm) {
            const int row_lo = q0 + wm + ra;
            const int row_hi = row_lo + 8;
#pragma unroll
            for (int nt = 0; nt < 8; nt++) {
                const int c = t0 + nt * 8 + kq;
                if (c > row_lo) s[nt][0] = -1e30f;
                if (c + 1 > row_lo) s[nt][1] = -1e30f;
                if (c > row_hi) s[nt][2] = -1e30f;
                if (c + 1 > row_hi) s[nt][3] = -1e30f;
            }
        }

        {
            float mt0 = -1e30f, mt1 = -1e30f;
#pragma unroll
            for (int nt = 0; nt < 8; nt++) {
                mt0 = fmaxf(mt0, fmaxf(s[nt][0], s[nt][1]));
                mt1 = fmaxf(mt1, fmaxf(s[nt][2], s[nt][3]));
            }
            mt0 = fmaxf(mt0, __shfl_xor_sync(0xffffffffu, mt0, 1));
            mt0 = fmaxf(mt0, __shfl_xor_sync(0xffffffffu, mt0, 2));
            mt1 = fmaxf(mt1, __shfl_xor_sync(0xffffffffu, mt1, 1));
            mt1 = fmaxf(mt1, __shfl_xor_sync(0xffffffffu, mt1, 2));
            const float mn0 = fmaxf(m_lo, mt0);
            const float mn1 = fmaxf(m_hi, mt1);
            const float al0 = __expf(m_lo - mn0);
            const float al1 = __expf(m_hi - mn1);
            float ls0 = 0.0f, ls1 = 0.0f;
#pragma unroll
            for (int nt = 0; nt < 8; nt++) {
                s[nt][0] = __expf(s[nt][0] - mn0);
                s[nt][1] = __expf(s[nt][1] - mn0);
                s[nt][2] = __expf(s[nt][2] - mn1);
                s[nt][3] = __expf(s[nt][3] - mn1);
                ls0 += s[nt][0] + s[nt][1];
                ls1 += s[nt][2] + s[nt][3];
            }
            ls0 += __shfl_xor_sync(0xffffffffu, ls0, 1);
            ls0 += __shfl_xor_sync(0xffffffffu, ls0, 2);
            ls1 += __shfl_xor_sync(0xffffffffu, ls1, 1);
            ls1 += __shfl_xor_sync(0xffffffffu, ls1, 2);
            l_lo = l_lo * al0 + ls0;
            l_hi = l_hi * al1 + ls1;
            m_lo = mn0; m_hi = mn1;
#pragma unroll
            for (int dn = 0; dn < 8; dn++) {
                o[dn][0] *= al0; o[dn][1] *= al0;
                o[dn][2] *= al1; o[dn][3] *= al1;
            }
        }

        uint32_t pf[4][4];
#pragma unroll
        for (int j = 0; j < 4; j++) {
            pf[j][0] = pack2h(__float2half_rn(s[2 * j][0]), __float2half_rn(s[2 * j][1]));
            pf[j][1] = pack2h(__float2half_rn(s[2 * j][2]), __float2half_rn(s[2 * j][3]));
            pf[j][2] = pack2h(__float2half_rn(s[2 * j + 1][0]), __float2half_rn(s[2 * j + 1][1]));
            pf[j][3] = pack2h(__float2half_rn(s[2 * j + 1][2]), __float2half_rn(s[2 * j + 1][3]));
        }

#pragma unroll
        for (int dp = 0; dp < 4; dp++) {
#pragma unroll
            for (int j = 0; j < 4; j++) {
                uint32_t v0f[2], v1f[2];
                ldmx4t(v0f[0], v0f[1], v1f[0], v1f[1],
                       smem_u32(&sV[(j * 16 + v_row) * 72 + dp * 16 + v_ch]));
                mma_f16(o[2 * dp], pf[j], v0f);
                mma_f16(o[2 * dp + 1], pf[j], v1f);
            }
        }
        __syncthreads();
    }

    const float il = 1.0f / l_lo;
    const float ih = 1.0f / l_hi;
    const size_t row_lo_g = rowb + wm + ra;
    const size_t row_hi_g = row_lo_g + 8;
#pragma unroll
    for (int dn = 0; dn < 8; dn++) {
        const int col = h * HD + dn * 8 + kq;
        *(uint32_t*)&g_ath[row_lo_g * DM + col] =
            pack2h(__float2half_rn(o[dn][0] * il), __float2half_rn(o[dn][1] * il));
        *(uint32_t*)&g_ath[row_hi_g * DM + col] =
            pack2h(__float2half_rn(o[dn][2] * ih), __float2half_rn(o[dn][3] * ih));
    }
}

// ---------------------------------------------------------------------------
// Launcher
// ---------------------------------------------------------------------------
extern "C" void kernel_launch(void* const* d_in, const int* in_sizes, int n_in,
                              void* d_out, int out_size)
{
    const float* x     = (const float*)d_in[0];
    const float* w_qkv = (const float*)d_in[1];
    const float* b_qkv = (const float*)d_in[2];
    const float* w_out = (const float*)d_in[3];
    const float* b_out = (const float*)d_in[4];
    float* out = (float*)d_out;

    __half *xh, *wqh, *woh, *wol, *ath;
    cudaGetSymbolAddress((void**)&xh, g_xh);
    cudaGetSymbolAddress((void**)&wqh, g_wqh);
    cudaGetSymbolAddress((void**)&woh, g_woh);
    cudaGetSymbolAddress((void**)&wol, g_wol);
    cudaGetSymbolAddress((void**)&ath, g_ath);

    cudaFuncSetAttribute(gemm_qkv, cudaFuncAttributeMaxDynamicSharedMemorySize, QKV_DSMEM);
    cudaFuncSetAttribute(gemm_out, cudaFuncAttributeMaxDynamicSharedMemorySize, OUT_DSMEM);
    cudaFuncSetAttribute(flash_attn_f16, cudaFuncAttributeMaxDynamicSharedMemorySize, ATTN_DSMEM);

    // Preprocessing (elementwise only)
    to_f16<<<(MROWS * KDIM / 4 + 255) / 256, 256>>>(x, xh, MROWS * KDIM);
    to_f16<<<(KDIM * QKV_N / 4 + 255) / 256, 256>>>(w_qkv, wqh, KDIM * QKV_N);
    split_f16<<<(KDIM * DM / 4 + 255) / 256, 256>>>(w_out, woh, wol, KDIM * DM);

    // 1) QKV projection (1-MMA fp16, trans-B, 3 CTAs/SM) -> g_qkvh
    gemm_qkv<<<dim3(QKV_N / 128, MROWS / 128), 256, QKV_DSMEM>>>(xh, wqh, b_qkv);

    // 2) Attention (1-MMA S, 1-MMA PV) -> g_ath
    flash_attn_f16<<<dim3(SEQ / 128, NH, BSZ), 256, ATTN_DSMEM>>>();

    // 3) Out projection (2-MMA fp16, trans-B, 3 CTAs/SM) -> fp32 output
    gemm_out<<<dim3(DM / 128, MROWS / 128), 256, OUT_DSMEM>>>(
        ath, woh, wol, b_out, out);
}

// round 17
// speedup vs baseline: 1.4258x; 1.4258x over previous
#include <cuda_runtime.h>
#include <cuda_fp16.h>
#include <cstdint>

// Problem constants
#define BSZ 2
#define SEQ 2048
#define DM 1024
#define NH 16
#define HD 64
#define MROWS 4096
#define QKV_N 3072
#define KDIM 1024

// ---------------------------------------------------------------------------
// Scratch (__device__ globals; allocation-free rule). Weights kept [K,N].
// ---------------------------------------------------------------------------
__device__ __align__(16) __half g_xh[MROWS * KDIM];        // x single fp16
__device__ __align__(16) __half g_wqh[KDIM * QKV_N];       // w_qkv [K,N] single
__device__ __align__(16) __half g_woh[KDIM * DM];          // w_out [K,N] hi
__device__ __align__(16) __half g_wol[KDIM * DM];          // w_out [K,N] lo
__device__ __align__(16) __half g_qkvh[MROWS * QKV_N];     // Q(scaled) K V single
__device__ __align__(16) __half g_ath[MROWS * DM];         // attn out single

// ---------------------------------------------------------------------------
// PTX helpers
// ---------------------------------------------------------------------------
__device__ __forceinline__ uint32_t smem_u32(const void* p) {
    uint32_t a;
    asm("{ .reg .u64 t; cvta.to.shared.u64 t, %1; cvt.u32.u64 %0, t; }" : "=r"(a) : "l"(p));
    return a;
}
__device__ __forceinline__ void ldmx4(uint32_t& r0, uint32_t& r1, uint32_t& r2,
                                      uint32_t& r3, uint32_t addr) {
    asm volatile("ldmatrix.sync.aligned.m8n8.x4.shared.b16 {%0,%1,%2,%3}, [%4];"
                 : "=r"(r0), "=r"(r1), "=r"(r2), "=r"(r3) : "r"(addr));
}
__device__ __forceinline__ void ldmx4t(uint32_t& r0, uint32_t& r1, uint32_t& r2,
                                       uint32_t& r3, uint32_t addr) {
    asm volatile("ldmatrix.sync.aligned.m8n8.x4.trans.shared.b16 {%0,%1,%2,%3}, [%4];"
                 : "=r"(r0), "=r"(r1), "=r"(r2), "=r"(r3) : "r"(addr));
}
__device__ __forceinline__ void mma_f16(float* c, const uint32_t* a, const uint32_t* b) {
    asm volatile(
        "mma.sync.aligned.m16n8k16.row.col.f32.f16.f16.f32 "
        "{%0,%1,%2,%3}, {%4,%5,%6,%7}, {%8,%9}, {%0,%1,%2,%3};"
        : "+f"(c[0]), "+f"(c[1]), "+f"(c[2]), "+f"(c[3])
        : "r"(a[0]), "r"(a[1]), "r"(a[2]), "r"(a[3]), "r"(b[0]), "r"(b[1]));
}
__device__ __forceinline__ void cp_async16(uint32_t saddr, const void* g) {
    asm volatile("cp.async.cg.shared.global [%0], [%1], 16;" :: "r"(saddr), "l"(g));
}
#define CP_COMMIT() asm volatile("cp.async.commit_group;" ::: "memory")
#define CP_WAIT(n)  asm volatile("cp.async.wait_group %0;" :: "n"(n) : "memory")

__device__ __forceinline__ uint32_t pack2h(__half a, __half b) {
    __half2 t = __halves2half2(a, b);
    return *reinterpret_cast<uint32_t*>(&t);
}
__device__ __forceinline__ void split2h(float a, float b, uint32_t& hi, uint32_t& lo) {
    __half ha = __float2half_rn(a), hb = __float2half_rn(b);
    hi = pack2h(ha, hb);
    lo = pack2h(__float2half_rn(a - __half2float(ha)),
                __float2half_rn(b - __half2float(hb)));
}

// ---------------------------------------------------------------------------
// Preprocessing (elementwise only — no transposes)
// ---------------------------------------------------------------------------
__global__ __launch_bounds__(256) void to_f16(
    const float* __restrict__ src, __half* __restrict__ dst, int n)
{
    int i = (blockIdx.x * 256 + threadIdx.x) * 4;
    if (i >= n) return;
    float4 v = *(const float4*)&src[i];
    uint2 o;
    o.x = pack2h(__float2half_rn(v.x), __float2half_rn(v.y));
    o.y = pack2h(__float2half_rn(v.z), __float2half_rn(v.w));
    *(uint2*)&dst[i] = o;
}

__global__ __launch_bounds__(256) void split_f16(
    const float* __restrict__ src, __half* __restrict__ hi,
    __half* __restrict__ lo, int n)
{
    int i = (blockIdx.x * 256 + threadIdx.x) * 4;
    if (i >= n) return;
    float4 v = *(const float4*)&src[i];
    uint32_t h0, l0, h1, l1;
    split2h(v.x, v.y, h0, l0);
    split2h(v.z, v.w, h1, l1);
    *(uint2*)&hi[i] = make_uint2(h0, h1);
    *(uint2*)&lo[i] = make_uint2(l0, l1);
}

// ---------------------------------------------------------------------------
// GEMM tiles: A [128 rows][BKP] (ldmx4), B [32 k-rows][BNP] (ldmx4t, [K,N]).
// 128x128 CTA, BK=32, 8 warps (2m x 4n), warp 64x32. 2-stage cp.async.
// Natural register allocation (~96 regs, 2 CTAs/SM) — no launch-bounds forcing.
// ---------------------------------------------------------------------------
#define BKP 40
#define BNP 136
#define TSA (128 * BKP)               // 5120 elems
#define TSB (32 * BNP)                // 4352 elems
#define Q_STG (TSA + TSB)             // 9472 elems
#define QKV_DSMEM (2 * Q_STG * 2)     // 37,888 B
#define O_STG (TSA + 2 * TSB)         // 13,824 elems
#define OUT_DSMEM (2 * O_STG * 2)     // 55,296 B

// ---------------------------------------------------------------------------
// QKV GEMM: A single x B single (trans-B), 1 MMA. 2-stage.
// ---------------------------------------------------------------------------
__global__ __launch_bounds__(256) void gemm_qkv(
    const __half* __restrict__ A, const __half* __restrict__ B,
    const float* __restrict__ bias)
{
    extern __shared__ __align__(16) __half qbase[];
    const int tid  = threadIdx.x;
    const int lane = tid & 31;
    const int wid  = tid >> 5;
    const int warp_m = (wid & 1) * 64;
    const int warp_n = (wid >> 1) * 32;
    const int brow = blockIdx.y * 128;
    const int bcol = blockIdx.x * 128;

    float acc[4][4][4];
#pragma unroll
    for (int mi = 0; mi < 4; mi++)
#pragma unroll
        for (int ni = 0; ni < 4; ni++)
#pragma unroll
            for (int j = 0; j < 4; j++) acc[mi][ni][j] = 0.0f;

    const int a_row = (lane & 7) + ((lane >> 3) & 1) * 8;
    const int a_kh  = (lane >> 4) * 8;
    const int trow  = lane & 15;
    const int tcol8 = ((lane >> 4) & 1) * 8;

#define Q_ISSUE(s_, buf_)                                                         \
    do {                                                                          \
        __half* st = qbase + (buf_) * Q_STG;                                      \
        _Pragma("unroll") for (int u = tid; u < 1024; u += 256) {                 \
            if (u < 512) {                                                        \
                const int row = u >> 2;                                           \
                const int c8 = (u & 3) * 8;                                       \
                const size_t ga = (size_t)(brow + row) * KDIM + (s_) * 32 + c8;   \
                cp_async16(smem_u32(st + row * BKP + c8), &A[ga]);                \
            } else {                                                              \
                const int v = u - 512;                                            \
                const int row = v >> 4;                                           \
                const int c8 = (v & 15) * 8;                                      \
                const size_t gb = (size_t)((s_) * 32 + row) * QKV_N + bcol + c8;  \
                cp_async16(smem_u32(st + TSA + row * BNP + c8), &B[gb]);          \
            }                                                                     \
        }                                                                         \
    } while (0)

    Q_ISSUE(0, 0);
    CP_COMMIT();
    const int NS = KDIM / 32;
    for (int s = 0; s < NS; s++) {
        if (s + 1 < NS) { Q_ISSUE(s + 1, (s + 1) & 1); CP_COMMIT(); CP_WAIT(1); }
        else { CP_WAIT(0); }
        __syncthreads();
        const __half* cA = qbase + (s & 1) * Q_STG;
        const __half* cB = qbase + (s & 1) * Q_STG + TSA;
#pragma unroll
        for (int kk = 0; kk < 2; kk++) {
            const int k0 = kk * 16;
            uint32_t af[4][4], bf[4][2];
#pragma unroll
            for (int mi = 0; mi < 4; mi++) {
                const int r = warp_m + mi * 16 + a_row;
                ldmx4(af[mi][0], af[mi][1], af[mi][2], af[mi][3],
                      smem_u32(&cA[r * BKP + k0 + a_kh]));
            }
#pragma unroll
            for (int pr = 0; pr < 2; pr++) {
                ldmx4t(bf[2 * pr][0], bf[2 * pr][1], bf[2 * pr + 1][0],
                       bf[2 * pr + 1][1],
                       smem_u32(&cB[(k0 + trow) * BNP + warp_n + pr * 16 + tcol8]));
            }
#pragma unroll
            for (int mi = 0; mi < 4; mi++)
#pragma unroll
                for (int ni = 0; ni < 4; ni++)
                    mma_f16(acc[mi][ni], af[mi], bf[ni]);
        }
        __syncthreads();
    }

    const int er = brow + warp_m + (lane >> 2);
    const int ec = bcol + warp_n + (lane & 3) * 2;
#pragma unroll
    for (int mi = 0; mi < 4; mi++)
#pragma unroll
        for (int ni = 0; ni < 4; ni++) {
            const int r0 = er + mi * 16;
            const int c0 = ec + ni * 8;
            float v0 = acc[mi][ni][0] + bias[c0];
            float v1 = acc[mi][ni][1] + bias[c0 + 1];
            float v2 = acc[mi][ni][2] + bias[c0];
            float v3 = acc[mi][ni][3] + bias[c0 + 1];
            if (c0 < DM) { v0 *= 0.03125f; v1 *= 0.03125f; v2 *= 0.03125f; v3 *= 0.03125f; }
            *(uint32_t*)&g_qkvh[(size_t)r0 * QKV_N + c0] =
                pack2h(__float2half_rn(v0), __float2half_rn(v1));
            *(uint32_t*)&g_qkvh[(size_t)(r0 + 8) * QKV_N + c0] =
                pack2h(__float2half_rn(v2), __float2half_rn(v3));
        }
}

// ---------------------------------------------------------------------------
// Out-proj GEMM: A single x B 2-term (trans-B), 2 MMAs. 2-stage.
// ---------------------------------------------------------------------------
__global__ __launch_bounds__(256) void gemm_out(
    const __half* __restrict__ A, const __half* __restrict__ Bh,
    const __half* __restrict__ Bl, const float* __restrict__ bias,
    float* __restrict__ C)
{
    extern __shared__ __align__(16) __half obase[];
    const int tid  = threadIdx.x;
    const int lane = tid & 31;
    const int wid  = tid >> 5;
    const int warp_m = (wid & 1) * 64;
    const int warp_n = (wid >> 1) * 32;
    const int brow = blockIdx.y * 128;
    const int bcol = blockIdx.x * 128;

    float acc[4][4][4];
#pragma unroll
    for (int mi = 0; mi < 4; mi++)
#pragma unroll
        for (int ni = 0; ni < 4; ni++)
#pragma unroll
            for (int j = 0; j < 4; j++) acc[mi][ni][j] = 0.0f;

    const int a_row = (lane & 7) + ((lane >> 3) & 1) * 8;
    const int a_kh  = (lane >> 4) * 8;
    const int trow  = lane & 15;
    const int tcol8 = ((lane >> 4) & 1) * 8;

#define O_ISSUE(s_, buf_)                                                         \
    do {                                                                          \
        __half* st = obase + (buf_) * O_STG;                                      \
        _Pragma("unroll") for (int u = tid; u < 1536; u += 256) {                 \
            if (u < 512) {                                                        \
                const int row = u >> 2;                                           \
                const int c8 = (u & 3) * 8;                                       \
                const size_t ga = (size_t)(brow + row) * KDIM + (s_) * 32 + c8;   \
                cp_async16(smem_u32(st + row * BKP + c8), &A[ga]);                \
            } else if (u < 1024) {                                                \
                const int v = u - 512;                                            \
                const int row = v >> 4;                                           \
                const int c8 = (v & 15) * 8;                                      \
                const size_t gb = (size_t)((s_) * 32 + row) * DM + bcol + c8;     \
                cp_async16(smem_u32(st + TSA + row * BNP + c8), &Bh[gb]);         \
            } else {                                                              \
                const int v = u - 1024;                                           \
                const int row = v >> 4;                                           \
                const int c8 = (v & 15) * 8;                                      \
                const size_t gb = (size_t)((s_) * 32 + row) * DM + bcol + c8;     \
                cp_async16(smem_u32(st + TSA + TSB + row * BNP + c8), &Bl[gb]);   \
            }                                                                     \
        }                                                                         \
    } while (0)

    O_ISSUE(0, 0);
    CP_COMMIT();
    const int NS = KDIM / 32;
    for (int s = 0; s < NS; s++) {
        if (s + 1 < NS) { O_ISSUE(s + 1, (s + 1) & 1); CP_COMMIT(); CP_WAIT(1); }
        else { CP_WAIT(0); }
        __syncthreads();
        const __half* cA  = obase + (s & 1) * O_STG;
        const __half* cBh = obase + (s & 1) * O_STG + TSA;
        const __half* cBl = obase + (s & 1) * O_STG + TSA + TSB;
#pragma unroll
        for (int kk = 0; kk < 2; kk++) {
            const int k0 = kk * 16;
            uint32_t af[4][4], bh[4][2], bl[4][2];
#pragma unroll
            for (int mi = 0; mi < 4; mi++) {
                const int r = warp_m + mi * 16 + a_row;
                ldmx4(af[mi][0], af[mi][1], af[mi][2], af[mi][3],
                      smem_u32(&cA[r * BKP + k0 + a_kh]));
            }
#pragma unroll
            for (int pr = 0; pr < 2; pr++) {
                const uint32_t off = (k0 + trow) * BNP + warp_n + pr * 16 + tcol8;
                ldmx4t(bh[2 * pr][0], bh[2 * pr][1], bh[2 * pr + 1][0],
                       bh[2 * pr + 1][1], smem_u32(&cBh[off]));
                ldmx4t(bl[2 * pr][0], bl[2 * pr][1], bl[2 * pr + 1][0],
                       bl[2 * pr + 1][1], smem_u32(&cBl[off]));
            }
#pragma unroll
            for (int mi = 0; mi < 4; mi++)
#pragma unroll
                for (int ni = 0; ni < 4; ni++) {
                    mma_f16(acc[mi][ni], af[mi], bh[ni]);
                    mma_f16(acc[mi][ni], af[mi], bl[ni]);
                }
        }
        __syncthreads();
    }

    const int er = brow + warp_m + (lane >> 2);
    const int ec = bcol + warp_n + (lane & 3) * 2;
#pragma unroll
    for (int mi = 0; mi < 4; mi++)
#pragma unroll
        for (int ni = 0; ni < 4; ni++) {
            const int r0 = er + mi * 16;
            const int c0 = ec + ni * 8;
            float2 v0, v1;
            v0.x = acc[mi][ni][0] + bias[c0];
            v0.y = acc[mi][ni][1] + bias[c0 + 1];
            v1.x = acc[mi][ni][2] + bias[c0];
            v1.y = acc[mi][ni][3] + bias[c0 + 1];
            *(float2*)&C[(size_t)r0 * DM + c0] = v0;
            *(float2*)&C[(size_t)(r0 + 8) * DM + c0] = v1;
        }
}

// ---------------------------------------------------------------------------
// Flash attention fp16 (validated R11, unchanged): S = QK 1 MMA, PV 1 MMA.
// ---------------------------------------------------------------------------
#define AT_TILE (64 * 72)
#define AT_STG (2 * AT_TILE)
#define ATTN_DSMEM (2 * AT_STG * 2)   // 36,864 B

__global__ __launch_bounds__(256) void flash_attn_f16()
{
    extern __shared__ __align__(16) __half abase[];

    const int tid = threadIdx.x, lane = tid & 31, wid = tid >> 5;
    const int qt = gridDim.x - 1 - blockIdx.x;
    const int h = blockIdx.y, b = blockIdx.z;
    const int q0 = qt * 128;
    const size_t rowb = (size_t)b * SEQ + q0;
    const int wm = wid * 16;
    const int ra = lane >> 2;
    const int kq = (lane & 3) * 2;

    uint32_t qf[4][4];
    {
        const size_t r0 = (rowb + wm + ra) * QKV_N + h * HD;
        const size_t r1 = (rowb + wm + ra + 8) * QKV_N + h * HD;
#pragma unroll
        for (int ks = 0; ks < 4; ks++) {
            const int c = ks * 16 + kq;
            qf[ks][0] = *(const uint32_t*)&g_qkvh[r0 + c];
            qf[ks][1] = *(const uint32_t*)&g_qkvh[r1 + c];
            qf[ks][2] = *(const uint32_t*)&g_qkvh[r0 + c + 8];
            qf[ks][3] = *(const uint32_t*)&g_qkvh[r1 + c + 8];
        }
    }

    float o[8][4];
#pragma unroll
    for (int dn = 0; dn < 8; dn++)
#pragma unroll
        for (int j = 0; j < 4; j++) o[dn][j] = 0.0f;
    float m_lo = -1e30f, m_hi = -1e30f, l_lo = 0.0f, l_hi = 0.0f;

    const int bx4_row = (lane & 7) + ((lane >> 4) & 1) * 8;
    const int b_kh = ((lane >> 3) & 1) * 8;
    const int v_row = lane & 15;
    const int v_ch = ((lane >> 4) & 1) * 8;

#define KV_ISSUE(kt_, buf_)                                                        \
    do {                                                                           \
        __half* st = abase + (buf_) * AT_STG;                                      \
        const size_t gr = (size_t)b * SEQ + (kt_) * 64;                            \
        _Pragma("unroll") for (int u = tid; u < 512; u += 256) {                   \
            const int row = u >> 3;                                                \
            const int c8 = (u & 7) * 8;                                            \
            const size_t gk = (gr + row) * QKV_N + DM + h * HD + c8;               \
            cp_async16(smem_u32(st + 0 * AT_TILE + row * 72 + c8), &g_qkvh[gk]);   \
            cp_async16(smem_u32(st + 1 * AT_TILE + row * 72 + c8), &g_qkvh[gk + DM]); \
        }                                                                          \
    } while (0)

    const int nkt = 2 * qt + 2;
    KV_ISSUE(0, 0);
    CP_COMMIT();

    for (int kt = 0; kt < nkt; kt++) {
        if (kt + 1 < nkt) { KV_ISSUE(kt + 1, (kt + 1) & 1); CP_COMMIT(); CP_WAIT(1); }
        else { CP_WAIT(0); }
        __syncthreads();
        const __half* sK = abase + (kt & 1) * AT_STG + 0 * AT_TILE;
        const __half* sV = abase + (kt & 1) * AT_STG + 1 * AT_TILE;
        const int t0 = kt * 64;

        float s[8][4];
#pragma unroll
        for (int nt = 0; nt < 8; nt++)
#pragma unroll
            for (int j = 0; j < 4; j++) s[nt][j] = 0.0f;
#pragma unroll
        for (int pr = 0; pr < 4; pr++) {
            const int r = pr * 16 + bx4_row;
#pragma unroll
            for (int ks = 0; ks < 4; ks++) {
                uint32_t k0f[2], k1f[2];
                ldmx4(k0f[0], k0f[1], k1f[0], k1f[1],
                      smem_u32(&sK[r * 72 + ks * 16 + b_kh]));
                mma_f16(s[2 * pr], qf[ks], k0f);
                mma_f16(s[2 * pr + 1], qf[ks], k1f);
            }
        }

        if (t0 + 63 > q0 + wm) {
            const int row_lo = q0 + wm + ra;
            const int row_hi = row_lo + 8;
#pragma unroll
            for (int nt = 0; nt < 8; nt++) {
                const int c = t0 + nt * 8 + kq;
                if (c > row_lo) s[nt][0] = -1e30f;
                if (c + 1 > row_lo) s[nt][1] = -1e30f;
                if (c > row_hi) s[nt][2] = -1e30f;
                if (c + 1 > row_hi) s[nt][3] = -1e30f;
            }
        }

        {
            float mt0 = -1e30f, mt1 = -1e30f;
#pragma unroll
            for (int nt = 0; nt < 8; nt++) {
                mt0 = fmaxf(mt0, fmaxf(s[nt][0], s[nt][1]));
                mt1 = fmaxf(mt1, fmaxf(s[nt][2], s[nt][3]));
            }
            mt0 = fmaxf(mt0, __shfl_xor_sync(0xffffffffu, mt0, 1));
            mt0 = fmaxf(mt0, __shfl_xor_sync(0xffffffffu, mt0, 2));
            mt1 = fmaxf(mt1, __shfl_xor_sync(0xffffffffu, mt1, 1));
            mt1 = fmaxf(mt1, __shfl_xor_sync(0xffffffffu, mt1, 2));
            const float mn0 = fmaxf(m_lo, mt0);
            const float mn1 = fmaxf(m_hi, mt1);
            const float al0 = __expf(m_lo - mn0);
            const float al1 = __expf(m_hi - mn1);
            float ls0 = 0.0f, ls1 = 0.0f;
#pragma unroll
            for (int nt = 0; nt < 8; nt++) {
                s[nt][0] = __expf(s[nt][0] - mn0);
                s[nt][1] = __expf(s[nt][1] - mn0);
                s[nt][2] = __expf(s[nt][2] - mn1);
                s[nt][3] = __expf(s[nt][3] - mn1);
                ls0 += s[nt][0] + s[nt][1];
                ls1 += s[nt][2] + s[nt][3];
            }
            ls0 += __shfl_xor_sync(0xffffffffu, ls0, 1);
            ls0 += __shfl_xor_sync(0xffffffffu, ls0, 2);
            ls1 += __shfl_xor_sync(0xffffffffu, ls1, 1);
            ls1 += __shfl_xor_sync(0xffffffffu, ls1, 2);
            l_lo = l_lo * al0 + ls0;
            l_hi = l_hi * al1 + ls1;
            m_lo = mn0; m_hi = mn1;
#pragma unroll
            for (int dn = 0; dn < 8; dn++) {
                o[dn][0] *= al0; o[dn][1] *= al0;
                o[dn][2] *= al1; o[dn][3] *= al1;
            }
        }

        uint32_t pf[4][4];
#pragma unroll
        for (int j = 0; j < 4; j++) {
            pf[j][0] = pack2h(__float2half_rn(s[2 * j][0]), __float2half_rn(s[2 * j][1]));
            pf[j][1] = pack2h(__float2half_rn(s[2 * j][2]), __float2half_rn(s[2 * j][3]));
            pf[j][2] = pack2h(__float2half_rn(s[2 * j + 1][0]), __float2half_rn(s[2 * j + 1][1]));
            pf[j][3] = pack2h(__float2half_rn(s[2 * j + 1][2]), __float2half_rn(s[2 * j + 1][3]));
        }

#pragma unroll
        for (int dp = 0; dp < 4; dp++) {
#pragma unroll
            for (int j = 0; j < 4; j++) {
                uint32_t v0f[2], v1f[2];
                ldmx4t(v0f[0], v0f[1], v1f[0], v1f[1],
                       smem_u32(&sV[(j * 16 + v_row) * 72 + dp * 16 + v_ch]));
                mma_f16(o[2 * dp], pf[j], v0f);
                mma_f16(o[2 * dp + 1], pf[j], v1f);
            }
        }
        __syncthreads();
    }

    const float il = 1.0f / l_lo;
    const float ih = 1.0f / l_hi;
    const size_t row_lo_g = rowb + wm + ra;
    const size_t row_hi_g = row_lo_g + 8;
#pragma unroll
    for (int dn = 0; dn < 8; dn++) {
        const int col = h * HD + dn * 8 + kq;
        *(uint32_t*)&g_ath[row_lo_g * DM + col] =
            pack2h(__float2half_rn(o[dn][0] * il), __float2half_rn(o[dn][1] * il));
        *(uint32_t*)&g_ath[row_hi_g * DM + col] =
            pack2h(__float2half_rn(o[dn][2] * ih), __float2half_rn(o[dn][3] * ih));
    }
}

// ---------------------------------------------------------------------------
// Launcher
// ---------------------------------------------------------------------------
extern "C" void kernel_launch(void* const* d_in, const int* in_sizes, int n_in,
                              void* d_out, int out_size)
{
    const float* x     = (const float*)d_in[0];
    const float* w_qkv = (const float*)d_in[1];
    const float* b_qkv = (const float*)d_in[2];
    const float* w_out = (const float*)d_in[3];
    const float* b_out = (const float*)d_in[4];
    float* out = (float*)d_out;

    __half *xh, *wqh, *woh, *wol, *ath;
    cudaGetSymbolAddress((void**)&xh, g_xh);
    cudaGetSymbolAddress((void**)&wqh, g_wqh);
    cudaGetSymbolAddress((void**)&woh, g_woh);
    cudaGetSymbolAddress((void**)&wol, g_wol);
    cudaGetSymbolAddress((void**)&ath, g_ath);

    cudaFuncSetAttribute(gemm_qkv, cudaFuncAttributeMaxDynamicSharedMemorySize, QKV_DSMEM);
    cudaFuncSetAttribute(gemm_out, cudaFuncAttributeMaxDynamicSharedMemorySize, OUT_DSMEM);
    cudaFuncSetAttribute(flash_attn_f16, cudaFuncAttributeMaxDynamicSharedMemorySize, ATTN_DSMEM);

    // Preprocessing (elementwise only)
    to_f16<<<(MROWS * KDIM / 4 + 255) / 256, 256>>>(x, xh, MROWS * KDIM);
    to_f16<<<(KDIM * QKV_N / 4 + 255) / 256, 256>>>(w_qkv, wqh, KDIM * QKV_N);
    split_f16<<<(KDIM * DM / 4 + 255) / 256, 256>>>(w_out, woh, wol, KDIM * DM);

    // 1) QKV projection (1-MMA fp16, trans-B, 2-stage) -> g_qkvh
    gemm_qkv<<<dim3(QKV_N / 128, MROWS / 128), 256, QKV_DSMEM>>>(xh, wqh, b_qkv);

    // 2) Attention (1-MMA S, 1-MMA PV) -> g_ath
    flash_attn_f16<<<dim3(SEQ / 128, NH, BSZ), 256, ATTN_DSMEM>>>();

    // 3) Out projection (2-MMA fp16, trans-B, 2-stage) -> fp32 output
    gemm_out<<<dim3(DM / 128, MROWS / 128), 256, OUT_DSMEM>>>(
        ath, woh, wol, b_out, out);
}